// round 3
// baseline (speedup 1.0000x reference)
#include <cuda_runtime.h>
#include <cuda_bf16.h>
#include <mma.h>
#include <cstddef>
using namespace nvcuda;

#define Bsz 256
#define Lsz 2048
#define BL  (Bsz*Lsz)   // 524288 tokens

// ---------------- scratch ----------------
__device__ float g_G[(size_t)256 * BL];   // gates token-major [tok][256]
__device__ float g_Hf[(size_t)BL * 64];
__device__ float g_Hb[(size_t)BL * 64];
__device__ float g_T[4 * 64 * 64];
__device__ float g_gateW[68 * 256];       // folded fp32 gate weights [k][256] (67 real + pad)
__device__ float g_gateB[256];
__device__ float g_headW[192 * 128];      // folded fp32 head weights [k][128]
__device__ float g_headB[128];
__device__ __nv_bfloat16 g_gateWh[80 * 256];
__device__ __nv_bfloat16 g_gateWl[80 * 256];
__device__ __nv_bfloat16 g_headWh[192 * 128];
__device__ __nv_bfloat16 g_headWl[192 * 128];

// ---------------- prep: fold weights (fp32, tiny) ----------------
__global__ void prepA_kernel(const float* fwz, const float* fbz, const float* fwh, const float* fbh,
                             const float* bwz, const float* bbz, const float* bwh, const float* bbh,
                             const float* fpw, const float* fpb, const float* bpw, const float* bpb)
{
    int tid = threadIdx.x;              // 256
    int g = tid >> 6, i = tid & 63;
    const float* A  = (g==0) ? fwz : (g==1) ? fwh : (g==2) ? bwz : bwh;
    const float* ab = (g==0) ? fbz : (g==1) ? fbh : (g==2) ? bbz : bbh;
    const float* P  = (g<2) ? fpw : bpw;
    const float* pb = (g<2) ? fpb : bpb;

    for (int j = 0; j < 64; ++j) {
        float s = 0.f;
        for (int h = 0; h < 64; ++h) s = fmaf(A[i*64+h], P[h*67 + 3 + j], s);
        g_T[(size_t)(g*64+i)*64 + j] = s;
    }
    for (int c = 0; c < 3; ++c) {
        float s = 0.f;
        for (int h = 0; h < 64; ++h) s = fmaf(A[i*64+h], P[h*67 + c], s);
        g_gateW[c*256 + g*64 + i] = s;
    }
    float s = ab[i];
    for (int h = 0; h < 64; ++h) s = fmaf(A[i*64+h], pb[h], s);
    g_gateB[g*64 + i] = s;
    g_gateW[67*256 + tid] = 0.f;
}

__global__ void prepB_kernel(const float* tew2, const float* teb2)
{
    int o = threadIdx.x;                // 256
    const float* T = &g_T[(size_t)o * 64];
    for (int k = 0; k < 64; ++k) {
        float s = 0.f;
        for (int j = 0; j < 64; ++j) s = fmaf(T[j], tew2[j*64 + k], s);
        g_gateW[(3+k)*256 + o] = s;
    }
    float s = 0.f;
    for (int j = 0; j < 64; ++j) s = fmaf(T[j], teb2[j], s);
    g_gateB[o] += s;
}

__global__ void prepHead_kernel(const float* ghw1, const float* ghb1,
                                const float* tew2, const float* teb2)
{
    int o = threadIdx.x;                // 128
    for (int k = 0; k < 128; ++k) g_headW[k*128 + o] = ghw1[o*192 + k];
    for (int k = 0; k < 64; ++k) {
        float s = 0.f;
        for (int j = 0; j < 64; ++j) s = fmaf(ghw1[o*192 + 128 + j], tew2[j*64 + k], s);
        g_headW[(128+k)*128 + o] = s;
    }
    float s = ghb1[o];
    for (int j = 0; j < 64; ++j) s = fmaf(ghw1[o*192 + 128 + j], teb2[j], s);
    g_headB[o] = s;
}

__global__ void convGate_kernel()
{
    int o = threadIdx.x;                // 256
    for (int k = 0; k < 80; ++k) {
        float w = (k < 67) ? g_gateW[k*256 + o] : 0.f;
        __nv_bfloat16 h = __float2bfloat16(w);
        g_gateWh[k*256 + o] = h;
        g_gateWl[k*256 + o] = __float2bfloat16(w - __bfloat162float(h));
    }
}

__global__ void convHead_kernel()
{
    int o = threadIdx.x;                // 128
    for (int k = 0; k < 192; ++k) {
        float w = g_headW[k*128 + o];
        __nv_bfloat16 h = __float2bfloat16(w);
        g_headWh[k*128 + o] = h;
        g_headWl[k*128 + o] = __float2bfloat16(w - __bfloat162float(h));
    }
}

// ---------------- gates: bf16x3 wmma GEMM, M=128 tok, N=256, K=80 ----------------
#define GA_LDA 88
#define GATES_SMEM 131072   // max(A 45056 + W 81920 = 126976, C 131072)

__global__ void __launch_bounds__(256, 1)
gates_kernel(const float* __restrict__ x, const float* __restrict__ tt,
             const float* __restrict__ mtok,
             const float* __restrict__ tew1, const float* __restrict__ teb1)
{
    extern __shared__ char smraw[];
    __nv_bfloat16* Ah = (__nv_bfloat16*)smraw;          // [128][88]
    __nv_bfloat16* Al = Ah + 128*GA_LDA;
    __nv_bfloat16* Wh = Al + 128*GA_LDA;                // [80][256]
    __nv_bfloat16* Wl = Wh + 80*256;
    float* Csm = (float*)smraw;                          // reuse: [128][256]
    __shared__ float bsm[256];
    __shared__ float te1[64], te1b[64];

    const int tid = threadIdx.x;
    const size_t base = (size_t)blockIdx.x * 128;

    {   // copy folded W hi/lo (2560 float4 each)
        const float4* sh = (const float4*)g_gateWh;
        const float4* sl = (const float4*)g_gateWl;
        float4* dh = (float4*)Wh;
        float4* dl = (float4*)Wl;
        for (int i = tid; i < 2560; i += 256) { dh[i] = sh[i]; dl[i] = sl[i]; }
    }
    if (tid < 64) { te1[tid] = tew1[tid]; te1b[tid] = teb1[tid]; }
    bsm[tid] = g_gateB[tid];
    __syncthreads();

    if (tid < 128) {    // build A row (token)
        const size_t g = base + tid;
        float m  = x[g*3 + 2];
        float x0 = x[g*3 + 0];
        float x1 = x[g*3 + 1];
        if (m == 0.f) { x0 = mtok[0]; x1 = mtok[1]; }
        float tv = tt[g];
        __nv_bfloat16* ah = Ah + tid*GA_LDA;
        __nv_bfloat16* al = Al + tid*GA_LDA;
        auto put = [&](int k, float v) {
            __nv_bfloat16 h = __float2bfloat16(v);
            ah[k] = h;
            al[k] = __float2bfloat16(v - __bfloat162float(h));
        };
        put(0, x0); put(1, x1); put(2, m);
#pragma unroll
        for (int j = 0; j < 64; ++j)
            put(3 + j, fmaxf(fmaf(te1[j], tv, te1b[j]), 0.f));
        const __nv_bfloat16 z = __float2bfloat16(0.f);
#pragma unroll
        for (int k = 67; k < 80; ++k) { ah[k] = z; al[k] = z; }
    }
    __syncthreads();

    const int wrp = tid >> 5;
    const int wm = wrp >> 2;    // 0..1
    const int wn = wrp & 3;     // 0..3

    wmma::fragment<wmma::accumulator,16,16,16,float> acc[4][4];
#pragma unroll
    for (int i = 0; i < 4; ++i)
#pragma unroll
        for (int j = 0; j < 4; ++j) wmma::fill_fragment(acc[i][j], 0.f);

#pragma unroll
    for (int ks = 0; ks < 5; ++ks) {
        wmma::fragment<wmma::matrix_a,16,16,16,__nv_bfloat16,wmma::row_major> fah[4], fal[4];
#pragma unroll
        for (int i = 0; i < 4; ++i) {
            wmma::load_matrix_sync(fah[i], Ah + (wm*64 + i*16)*GA_LDA + ks*16, GA_LDA);
            wmma::load_matrix_sync(fal[i], Al + (wm*64 + i*16)*GA_LDA + ks*16, GA_LDA);
        }
#pragma unroll
        for (int j = 0; j < 4; ++j) {
            wmma::fragment<wmma::matrix_b,16,16,16,__nv_bfloat16,wmma::row_major> fbh, fbl;
            wmma::load_matrix_sync(fbh, Wh + (ks*16)*256 + wn*64 + j*16, 256);
            wmma::load_matrix_sync(fbl, Wl + (ks*16)*256 + wn*64 + j*16, 256);
#pragma unroll
            for (int i = 0; i < 4; ++i) {
                wmma::mma_sync(acc[i][j], fah[i], fbh, acc[i][j]);
                wmma::mma_sync(acc[i][j], fah[i], fbl, acc[i][j]);
                wmma::mma_sync(acc[i][j], fal[i], fbh, acc[i][j]);
            }
        }
    }
    __syncthreads();   // A/W dead, reuse as Csm
#pragma unroll
    for (int i = 0; i < 4; ++i)
#pragma unroll
        for (int j = 0; j < 4; ++j)
            wmma::store_matrix_sync(Csm + (wm*64 + i*16)*256 + wn*64 + j*16,
                                    acc[i][j], 256, wmma::mem_row_major);
    __syncthreads();

    // epilogue: bias + activation + store token-major
    const int lane = tid & 31;
    const int o0 = lane * 8;
    const bool sig = ((lane >> 3) & 1) == 0;
    float bb[8];
#pragma unroll
    for (int oi = 0; oi < 8; ++oi) bb[oi] = bsm[o0 + oi];

    for (int tok = wrp; tok < 128; tok += 8) {
        float4 c0 = *(float4*)&Csm[tok*256 + o0];
        float4 c1 = *(float4*)&Csm[tok*256 + o0 + 4];
        float v[8] = {c0.x,c0.y,c0.z,c0.w,c1.x,c1.y,c1.z,c1.w};
#pragma unroll
        for (int oi = 0; oi < 8; ++oi) {
            float u = v[oi] + bb[oi];
            if (sig) {
                u = __fdividef(1.f, 1.f + __expf(-u));
            } else {
                float e = __expf(-2.f * fabsf(u));
                u = copysignf(__fdividef(1.f - e, 1.f + e), u);
            }
            v[oi] = u;
        }
        float* dst = &g_G[(base + tok)*256 + o0];
        *(float4*)(dst)     = make_float4(v[0], v[1], v[2], v[3]);
        *(float4*)(dst + 4) = make_float4(v[4], v[5], v[6], v[7]);
    }
}

// ---------------- scan (unchanged, passed R2) ----------------
__global__ void __launch_bounds__(128, 8)
scan_kernel()
{
    const int b   = blockIdx.x;
    const int dir = threadIdx.x >> 6;
    const int ch  = threadIdx.x & 63;
    const float* Gz = g_G + (size_t)b*Lsz*256 + dir*128 + ch;
    float* Hout = (dir ? g_Hb : g_Hf) + (size_t)b*Lsz*64 + ch;

#define ROWOF(s) ((size_t)(dir ? (Lsz-1-(s)) : (s)))
    float zb[2][8], qb[2][8];
#pragma unroll
    for (int u = 0; u < 8; ++u) {
        size_t r = ROWOF(u) * 256;
        zb[0][u] = Gz[r];
        qb[0][u] = Gz[r + 64];
    }
    float h = 0.f;
    for (int t = 0; t < Lsz; t += 8) {
        const int cur = (t >> 3) & 1;
        if (t + 8 < Lsz) {
#pragma unroll
            for (int u = 0; u < 8; ++u) {
                size_t r = ROWOF(t + 8 + u) * 256;
                zb[cur^1][u] = Gz[r];
                qb[cur^1][u] = Gz[r + 64];
            }
        }
#pragma unroll
        for (int u = 0; u < 8; ++u) {
            Hout[ROWOF(t + u) * 64] = h;
            h = fmaf(zb[cur][u], qb[cur][u] - h, h);
        }
    }
#undef ROWOF
}

// ---------------- head: bf16x3 wmma GEMM, M=128 tok, N=128, K=192 + fused reduce ----------------
#define HA_LDA 200
#define HC_LDC 132
#define HEAD_SMEM 200704   // A 102400 + W 98304; C(128*132*4=67584) reuses A

__global__ void __launch_bounds__(256, 1)
head_kernel(const float* __restrict__ x, const float* __restrict__ tt,
            const float* __restrict__ tew1, const float* __restrict__ teb1,
            const float* __restrict__ ghw2, const float* __restrict__ ghb2,
            float* __restrict__ out)
{
    extern __shared__ char smraw[];
    __nv_bfloat16* Ah = (__nv_bfloat16*)smraw;          // [128][200]
    __nv_bfloat16* Al = Ah + 128*HA_LDA;
    __nv_bfloat16* Wh = Al + 128*HA_LDA;                // [192][128]
    __nv_bfloat16* Wl = Wh + 192*128;
    float* Csm = (float*)smraw;                          // reuse: [128][132]
    __shared__ __align__(16) float hff[64];
    __shared__ __align__(16) float hbf[64];
    __shared__ float te1[64], te1b[64];
    __shared__ float w2sm[128], hbsm[128];

    const int tid = threadIdx.x;
    const size_t base = (size_t)blockIdx.x * 128;
    const int b = (int)(base / Lsz);

    {   // copy head W hi/lo (3072 float4 each)
        const float4* sh = (const float4*)g_headWh;
        const float4* sl = (const float4*)g_headWl;
        float4* dh = (float4*)Wh;
        float4* dl = (float4*)Wl;
        for (int i = tid; i < 3072; i += 256) { dh[i] = sh[i]; dl[i] = sl[i]; }
    }
    if (tid < 64) {
        te1[tid] = tew1[tid]; te1b[tid] = teb1[tid];
        hff[tid] = g_Hf[((size_t)b*Lsz + (Lsz-1))*64 + tid];
        hbf[tid] = g_Hb[(size_t)b*Lsz*64 + tid];
    }
    if (tid < 128) { w2sm[tid] = ghw2[tid]; hbsm[tid] = g_headB[tid]; }
    __syncthreads();

    if (tid < 128) {    // build A row (token): [h_fwd(64)|h_bwd(64)|r(64)]
        const size_t g = base + tid;
        const float m = x[g*3 + 2];
        const bool um = m > 0.f;
        const float tv = tt[g];
        __nv_bfloat16* ah = Ah + tid*HA_LDA;
        __nv_bfloat16* al = Al + tid*HA_LDA;
        auto put = [&](int k, float v) {
            __nv_bfloat16 h = __float2bfloat16(v);
            ah[k] = h;
            al[k] = __float2bfloat16(v - __bfloat162float(h));
        };
        const float* sf = g_Hf + g*64;
        const float* sb = g_Hb + g*64;
#pragma unroll 8
        for (int k = 0; k < 64; ++k) put(k,      um ? sf[k] : hff[k]);
#pragma unroll 8
        for (int k = 0; k < 64; ++k) put(64 + k, um ? sb[k] : hbf[k]);
#pragma unroll
        for (int j = 0; j < 64; ++j)
            put(128 + j, fmaxf(fmaf(te1[j], tv, te1b[j]), 0.f));
    }
    __syncthreads();

    const int wrp = tid >> 5;
    const int wm = wrp >> 2;    // 0..1 (rows)
    const int wn = wrp & 3;     // 0..3 (cols, 32 each)

    wmma::fragment<wmma::accumulator,16,16,16,float> acc[4][2];
#pragma unroll
    for (int i = 0; i < 4; ++i)
#pragma unroll
        for (int j = 0; j < 2; ++j) wmma::fill_fragment(acc[i][j], 0.f);

#pragma unroll
    for (int ks = 0; ks < 12; ++ks) {
        wmma::fragment<wmma::matrix_a,16,16,16,__nv_bfloat16,wmma::row_major> fah[4], fal[4];
#pragma unroll
        for (int i = 0; i < 4; ++i) {
            wmma::load_matrix_sync(fah[i], Ah + (wm*64 + i*16)*HA_LDA + ks*16, HA_LDA);
            wmma::load_matrix_sync(fal[i], Al + (wm*64 + i*16)*HA_LDA + ks*16, HA_LDA);
        }
#pragma unroll
        for (int j = 0; j < 2; ++j) {
            wmma::fragment<wmma::matrix_b,16,16,16,__nv_bfloat16,wmma::row_major> fbh, fbl;
            wmma::load_matrix_sync(fbh, Wh + (ks*16)*128 + wn*32 + j*16, 128);
            wmma::load_matrix_sync(fbl, Wl + (ks*16)*128 + wn*32 + j*16, 128);
#pragma unroll
            for (int i = 0; i < 4; ++i) {
                wmma::mma_sync(acc[i][j], fah[i], fbh, acc[i][j]);
                wmma::mma_sync(acc[i][j], fah[i], fbl, acc[i][j]);
                wmma::mma_sync(acc[i][j], fal[i], fbh, acc[i][j]);
            }
        }
    }
    __syncthreads();
#pragma unroll
    for (int i = 0; i < 4; ++i)
#pragma unroll
        for (int j = 0; j < 2; ++j)
            wmma::store_matrix_sync(Csm + (wm*64 + i*16)*HC_LDC + wn*32 + j*16,
                                    acc[i][j], HC_LDC, wmma::mem_row_major);
    __syncthreads();

    // fused epilogue: out[tok] = ghb2 + sum_o w2[o]*relu(C[tok][o] + hb[o])
    const int token = tid >> 1;
    const int half  = tid & 1;
    float s = 0.f;
#pragma unroll
    for (int o4 = 0; o4 < 64; o4 += 4) {
        const int o = half*64 + o4;
        float4 c = *(float4*)&Csm[token*HC_LDC + o];
        s = fmaf(w2sm[o+0], fmaxf(c.x + hbsm[o+0], 0.f), s);
        s = fmaf(w2sm[o+1], fmaxf(c.y + hbsm[o+1], 0.f), s);
        s = fmaf(w2sm[o+2], fmaxf(c.z + hbsm[o+2], 0.f), s);
        s = fmaf(w2sm[o+3], fmaxf(c.w + hbsm[o+3], 0.f), s);
    }
    s += __shfl_xor_sync(0xffffffffu, s, 1);
    if (half == 0) out[base + token] = s + ghb2[0];
}

// ---------------- launch ----------------
extern "C" void kernel_launch(void* const* d_in, const int* in_sizes, int n_in,
                              void* d_out, int out_size)
{
    (void)in_sizes; (void)n_in; (void)out_size;
    const float* x    = (const float*)d_in[0];
    const float* t    = (const float*)d_in[1];
    const float* mtok = (const float*)d_in[2];
    const float* tew1 = (const float*)d_in[3];
    const float* teb1 = (const float*)d_in[4];
    const float* tew2 = (const float*)d_in[5];
    const float* teb2 = (const float*)d_in[6];
    const float* fpw  = (const float*)d_in[7];
    const float* fpb  = (const float*)d_in[8];
    const float* bpw  = (const float*)d_in[9];
    const float* bpb  = (const float*)d_in[10];
    const float* fwz  = (const float*)d_in[11];
    const float* fbz  = (const float*)d_in[12];
    const float* fwh  = (const float*)d_in[13];
    const float* fbh  = (const float*)d_in[14];
    const float* bwz  = (const float*)d_in[15];
    const float* bbz  = (const float*)d_in[16];
    const float* bwh  = (const float*)d_in[17];
    const float* bbh  = (const float*)d_in[18];
    const float* ghw1 = (const float*)d_in[19];
    const float* ghb1 = (const float*)d_in[20];
    const float* ghw2 = (const float*)d_in[21];
    const float* ghb2 = (const float*)d_in[22];
    float* out = (float*)d_out;

    cudaFuncSetAttribute(gates_kernel, cudaFuncAttributeMaxDynamicSharedMemorySize, GATES_SMEM);
    cudaFuncSetAttribute(head_kernel,  cudaFuncAttributeMaxDynamicSharedMemorySize, HEAD_SMEM);

    prepA_kernel<<<1, 256>>>(fwz, fbz, fwh, fbh, bwz, bbz, bwh, bbh, fpw, fpb, bpw, bpb);
    prepB_kernel<<<1, 256>>>(tew2, teb2);
    convGate_kernel<<<1, 256>>>();
    prepHead_kernel<<<1, 128>>>(ghw1, ghb1, tew2, teb2);
    convHead_kernel<<<1, 128>>>();

    gates_kernel<<<BL/128, 256, GATES_SMEM>>>(x, t, mtok, tew1, teb1);
    scan_kernel<<<Bsz, 128>>>();
    head_kernel<<<BL/128, 256, HEAD_SMEM>>>(x, t, tew1, teb1, ghw2, ghb2, out);
}

// round 4
// speedup vs baseline: 2.0194x; 2.0194x over previous
#include <cuda_runtime.h>
#include <cstddef>

#define Bsz 256
#define Lsz 2048
#define BL  (Bsz*Lsz)   // 524288 tokens

// ---------------- scratch ----------------
__device__ float g_Hf[(size_t)BL * 64];   // forward prestates, token-major [BL][64]
__device__ float g_Hb[(size_t)BL * 64];   // backward prestates
__device__ float g_T[4 * 64 * 64];
__device__ float g_gateW[68 * 256];       // folded gate weights [k][256]; cols: zf|htf|zb|htb
__device__ float g_gateB[256];
__device__ float g_headW[192 * 128];      // folded head weights [k][128]
__device__ float g_headB[128];

// ---------------- prep (parallelized) ----------------
// grid 68 x 256 threads
__global__ void prepA_kernel(const float* fwz, const float* fbz, const float* fwh, const float* fbh,
                             const float* bwz, const float* bbz, const float* bwh, const float* bbh,
                             const float* fpw, const float* fpb, const float* bpw, const float* bpb)
{
    const int tid = threadIdx.x;
    const int g = tid >> 6, i = tid & 63;
    const int bid = blockIdx.x;
    const float* A  = (g==0) ? fwz : (g==1) ? fwh : (g==2) ? bwz : bwh;
    const float* ab = (g==0) ? fbz : (g==1) ? fbh : (g==2) ? bbz : bbh;
    const float* P  = (g<2) ? fpw : bpw;
    const float* pb = (g<2) ? fpb : bpb;

    if (bid < 64) {                     // g_T[:, j=bid]
        const int j = bid;
        float s = 0.f;
#pragma unroll 8
        for (int h = 0; h < 64; ++h) s = fmaf(A[i*64+h], P[h*67 + 3 + j], s);
        g_T[(size_t)(g*64+i)*64 + j] = s;
    } else if (bid < 67) {              // x-columns
        const int c = bid - 64;
        float s = 0.f;
#pragma unroll 8
        for (int h = 0; h < 64; ++h) s = fmaf(A[i*64+h], P[h*67 + c], s);
        g_gateW[c*256 + g*64 + i] = s;
    } else {                            // bias + pad row
        float s = ab[i];
#pragma unroll 8
        for (int h = 0; h < 64; ++h) s = fmaf(A[i*64+h], pb[h], s);
        g_gateB[g*64 + i] = s;
        g_gateW[67*256 + tid] = 0.f;
    }
}

// grid 65 x 256 threads (after prepA)
__global__ void prepB_kernel(const float* tew2, const float* teb2)
{
    const int o = threadIdx.x;
    const int bid = blockIdx.x;
    const float* T = &g_T[(size_t)o * 64];
    if (bid < 64) {
        const int k = bid;
        float s = 0.f;
#pragma unroll 8
        for (int j = 0; j < 64; ++j) s = fmaf(T[j], tew2[j*64 + k], s);
        g_gateW[(3+k)*256 + o] = s;
    } else {
        float s = 0.f;
#pragma unroll 8
        for (int j = 0; j < 64; ++j) s = fmaf(T[j], teb2[j], s);
        g_gateB[o] += s;
    }
}

// grid 66 x 128 threads
__global__ void prepHead_kernel(const float* ghw1, const float* ghb1,
                                const float* tew2, const float* teb2)
{
    const int o = threadIdx.x;
    const int bid = blockIdx.x;
    if (bid < 64) {
        const int k = bid;
        float s = 0.f;
#pragma unroll 8
        for (int j = 0; j < 64; ++j) s = fmaf(ghw1[o*192 + 128 + j], tew2[j*64 + k], s);
        g_headW[(128+k)*128 + o] = s;
    } else if (bid == 64) {
        for (int k = 0; k < 128; ++k) g_headW[k*128 + o] = ghw1[o*192 + k];
    } else {
        float s = ghb1[o];
#pragma unroll 8
        for (int j = 0; j < 64; ++j) s = fmaf(ghw1[o*192 + 128 + j], teb2[j], s);
        g_headB[o] = s;
    }
}

// ---------------- fused gates GEMM + scan ----------------
// grid (256, 2): block = (batch b, direction). 512 threads, 2 blocks/SM.
// Per 128-token chunk: build A[68][132] -> GEMM 128outs x 128toks -> z into A-region, ht into hsm -> scan.
#define A_LD 132
#define Z_LD 129
#define FUSED_SMEM ((68*128 + 68*A_LD + 64*Z_LD) * 4)   // W + A(reused as z) + h  = 103744 B

__global__ void __launch_bounds__(512, 2)
fused_kernel(const float* __restrict__ x, const float* __restrict__ tt,
             const float* __restrict__ mtok,
             const float* __restrict__ tew1, const float* __restrict__ teb1)
{
    extern __shared__ float sm[];
    float* Wsm = sm;                 // [68][128]
    float* Asm = sm + 68*128;        // [68][132], reused as zsm [64][129] post-GEMM
    float* hsm = Asm + 68*A_LD;      // [64][129]
    __shared__ float bsm[128], te1[64], te1b[64], tvv[128];
    __shared__ float mtk[2];

    const int tid = threadIdx.x;
    const int b = blockIdx.x;
    const int dir = blockIdx.y;

    for (int i = tid; i < 68*32; i += 512) {     // 32 float4 per row of 128
        int k = i >> 5, q = i & 31;
        ((float4*)(Wsm + k*128))[q] = ((const float4*)(g_gateW + k*256 + dir*128))[q];
    }
    if (tid < 128) bsm[tid] = g_gateB[dir*128 + tid];
    if (tid < 64) { te1[tid] = tew1[tid]; te1b[tid] = teb1[tid]; }
    if (tid < 2)  mtk[tid] = mtok[tid];
    __syncthreads();

    const int lane = tid & 31;
    const int wrp  = tid >> 5;
    const int o0 = lane * 4;
    const int t0 = wrp * 8;
    float* Hout = (dir ? g_Hb : g_Hf) + (size_t)b * Lsz * 64;
    float hcar = 0.f;

    for (int ci = 0; ci < 16; ++ci) {
        const int c = dir ? (15 - ci) : ci;
        const size_t gb = (size_t)b * Lsz + (size_t)c * 128;

        if (tid < 128) {
            const size_t g = gb + tid;
            float m  = x[g*3 + 2];
            float x0 = x[g*3 + 0];
            float x1 = x[g*3 + 1];
            if (m == 0.f) { x0 = mtk[0]; x1 = mtk[1]; }
            Asm[0*A_LD + tid] = x0;
            Asm[1*A_LD + tid] = x1;
            Asm[2*A_LD + tid] = m;
            Asm[67*A_LD + tid] = 0.f;
            tvv[tid] = tt[g];
        }
        __syncthreads();
        for (int idx = tid; idx < 64*128; idx += 512) {
            int k = idx >> 7, tok = idx & 127;
            Asm[(3+k)*A_LD + tok] = fmaxf(fmaf(te1[k], tvv[tok], te1b[k]), 0.f);
        }
        __syncthreads();

        float acc[4][8];
#pragma unroll
        for (int i = 0; i < 4; ++i)
#pragma unroll
            for (int j = 0; j < 8; ++j) acc[i][j] = 0.f;

#pragma unroll 4
        for (int k = 0; k < 68; ++k) {
            float4 wv = *(const float4*)&Wsm[k*128 + o0];
            float4 a0 = *(const float4*)&Asm[k*A_LD + t0];
            float4 a1 = *(const float4*)&Asm[k*A_LD + t0 + 4];
            float a[8] = {a0.x,a0.y,a0.z,a0.w,a1.x,a1.y,a1.z,a1.w};
            float w[4] = {wv.x,wv.y,wv.z,wv.w};
#pragma unroll
            for (int oi = 0; oi < 4; ++oi)
#pragma unroll
                for (int tj = 0; tj < 8; ++tj)
                    acc[oi][tj] = fmaf(w[oi], a[tj], acc[oi][tj]);
        }
        __syncthreads();   // A dead -> reuse as z buffer

        {   // epilogue: bias + activation, write [ch][tok]
            const bool isz = (lane < 16);      // o<64 -> z (sigmoid), else htilde (tanh)
            float* dst = isz ? Asm : hsm;
            const int chn = isz ? o0 : (o0 - 64);
#pragma unroll
            for (int oi = 0; oi < 4; ++oi) {
                const float bb = bsm[o0 + oi];
#pragma unroll
                for (int tj = 0; tj < 8; ++tj) {
                    float v = acc[oi][tj] + bb;
                    if (isz) {
                        v = __fdividef(1.f, 1.f + __expf(-v));
                    } else {
                        float e = __expf(-2.f * fabsf(v));
                        v = copysignf(__fdividef(1.f - e, 1.f + e), v);
                    }
                    dst[(chn + oi)*Z_LD + t0 + tj] = v;
                }
            }
        }
        __syncthreads();

        if (tid < 64) {    // scan this chunk; ch = tid
            const float* zr = Asm + tid*Z_LD;
            const float* qr = hsm + tid*Z_LD;
            float* ho = Hout + (size_t)c*128*64 + tid;
            float h = hcar;
            if (dir == 0) {
#pragma unroll 4
                for (int t = 0; t < 128; ++t) {
                    ho[(size_t)t*64] = h;
                    h = fmaf(zr[t], qr[t] - h, h);
                }
            } else {
#pragma unroll 4
                for (int t = 127; t >= 0; --t) {
                    ho[(size_t)t*64] = h;
                    h = fmaf(zr[t], qr[t] - h, h);
                }
            }
            hcar = h;
        }
        __syncthreads();
    }
}

// ---------------- head GEMM (R2 proven code): 128 outs x K=192 + fused 128->1 reduce ----------------
#define HEAD_SMEM ((192*128 + 192*128) * 4)

__global__ void __launch_bounds__(512, 1)
head_kernel(const float* __restrict__ x, const float* __restrict__ tt,
            const float* __restrict__ tew1, const float* __restrict__ teb1,
            const float* __restrict__ ghw2, const float* __restrict__ ghb2,
            float* __restrict__ out)
{
    extern __shared__ float sm[];
    float* Wsm = sm;                      // [192][128]
    float* Asm = Wsm + 192*128;           // [192][128]
    __shared__ __align__(16) float hff[64];
    __shared__ __align__(16) float hbf[64];
    __shared__ float tv[128];
    __shared__ float w2sm[128];
    __shared__ float bsm[128];
    const int tid = threadIdx.x;
    const size_t base = (size_t)blockIdx.x * 128;
    const int b = (int)(base / Lsz);

    for (int i = tid; i < 192*128/4; i += 512)
        ((float4*)Wsm)[i] = ((const float4*)g_headW)[i];

    if (tid < 64)        hff[tid]      = g_Hf[((size_t)b*Lsz + (Lsz-1))*64 + tid];
    else if (tid < 128)  hbf[tid - 64] = g_Hb[(size_t)b*Lsz*64 + (tid - 64)];
    else if (tid < 256)  tv[tid - 128] = tt[base + tid - 128];
    else if (tid < 384)  w2sm[tid-256] = ghw2[(tid-256) & 127];
    if (tid >= 384)      bsm[tid-384]  = g_headB[tid-384];
    __syncthreads();

    {
        const int tok  = tid & 127;
        const int part = tid >> 7;
        if (part < 2) {
            const size_t g = base + tok;
            const float m  = x[g*3 + 2];
            const bool um  = m > 0.f;
            const float* src = (part ? g_Hb : g_Hf) + g * 64;
            const float* fin = part ? hbf : hff;
#pragma unroll
            for (int k = 0; k < 64; k += 4) {
                float4 v = *(const float4*)(src + k);
                float4 f = *(const float4*)(fin + k);
                float4 w = um ? v : f;
                int row = part*64 + k;
                Asm[(row+0)*128 + tok] = w.x;
                Asm[(row+1)*128 + tok] = w.y;
                Asm[(row+2)*128 + tok] = w.z;
                Asm[(row+3)*128 + tok] = w.w;
            }
        } else {
            const int k0 = (part - 2) * 32;
#pragma unroll
            for (int kk = 0; kk < 32; ++kk) {
                int k = k0 + kk;
                Asm[(128+k)*128 + tok] = fmaxf(fmaf(tew1[k], tv[tok], teb1[k]), 0.f);
            }
        }
    }
    __syncthreads();

    const int lane = tid & 31;
    const int wrp  = tid >> 5;
    const int o0 = lane * 4;
    const int t0 = wrp * 8;
    float acc[4][8];
#pragma unroll
    for (int i = 0; i < 4; ++i)
#pragma unroll
        for (int j = 0; j < 8; ++j) acc[i][j] = 0.f;

#pragma unroll 4
    for (int k = 0; k < 192; ++k) {
        float4 wv = *(const float4*)&Wsm[k*128 + o0];
        float4 a0 = *(const float4*)&Asm[k*128 + t0];
        float4 a1 = *(const float4*)&Asm[k*128 + t0 + 4];
        float a[8] = {a0.x,a0.y,a0.z,a0.w,a1.x,a1.y,a1.z,a1.w};
        float w[4] = {wv.x,wv.y,wv.z,wv.w};
#pragma unroll
        for (int oi = 0; oi < 4; ++oi)
#pragma unroll
            for (int tj = 0; tj < 8; ++tj)
                acc[oi][tj] = fmaf(w[oi], a[tj], acc[oi][tj]);
    }

    float w2[4], bb[4];
#pragma unroll
    for (int oi = 0; oi < 4; ++oi) { w2[oi] = w2sm[o0+oi]; bb[oi] = bsm[o0+oi]; }
    const float outb = ghb2[0];

#pragma unroll
    for (int tj = 0; tj < 8; ++tj) {
        float s = 0.f;
#pragma unroll
        for (int oi = 0; oi < 4; ++oi)
            s = fmaf(w2[oi], fmaxf(acc[oi][tj] + bb[oi], 0.f), s);
#pragma unroll
        for (int off = 16; off > 0; off >>= 1)
            s += __shfl_xor_sync(0xffffffffu, s, off);
        if (lane == 0) out[base + t0 + tj] = s + outb;
    }
}

// ---------------- launch ----------------
extern "C" void kernel_launch(void* const* d_in, const int* in_sizes, int n_in,
                              void* d_out, int out_size)
{
    (void)in_sizes; (void)n_in; (void)out_size;
    const float* x    = (const float*)d_in[0];
    const float* t    = (const float*)d_in[1];
    const float* mtok = (const float*)d_in[2];
    const float* tew1 = (const float*)d_in[3];
    const float* teb1 = (const float*)d_in[4];
    const float* tew2 = (const float*)d_in[5];
    const float* teb2 = (const float*)d_in[6];
    const float* fpw  = (const float*)d_in[7];
    const float* fpb  = (const float*)d_in[8];
    const float* bpw  = (const float*)d_in[9];
    const float* bpb  = (const float*)d_in[10];
    const float* fwz  = (const float*)d_in[11];
    const float* fbz  = (const float*)d_in[12];
    const float* fwh  = (const float*)d_in[13];
    const float* fbh  = (const float*)d_in[14];
    const float* bwz  = (const float*)d_in[15];
    const float* bbz  = (const float*)d_in[16];
    const float* bwh  = (const float*)d_in[17];
    const float* bbh  = (const float*)d_in[18];
    const float* ghw1 = (const float*)d_in[19];
    const float* ghb1 = (const float*)d_in[20];
    const float* ghw2 = (const float*)d_in[21];
    const float* ghb2 = (const float*)d_in[22];
    float* out = (float*)d_out;

    cudaFuncSetAttribute(fused_kernel, cudaFuncAttributeMaxDynamicSharedMemorySize, FUSED_SMEM);
    cudaFuncSetAttribute(head_kernel,  cudaFuncAttributeMaxDynamicSharedMemorySize, HEAD_SMEM);

    prepA_kernel<<<68, 256>>>(fwz, fbz, fwh, fbh, bwz, bbz, bwh, bbh, fpw, fpb, bpw, bpb);
    prepB_kernel<<<65, 256>>>(tew2, teb2);
    prepHead_kernel<<<66, 128>>>(ghw1, ghb1, tew2, teb2);

    fused_kernel<<<dim3(Bsz, 2), 512, FUSED_SMEM>>>(x, t, mtok, tew1, teb1);
    head_kernel<<<BL/128, 512, HEAD_SMEM>>>(x, t, tew1, teb1, ghw2, ghb2, out);
}

// round 5
// speedup vs baseline: 3.4155x; 1.6913x over previous
#include <cuda_runtime.h>
#include <cstddef>

#define Bsz 256
#define Lsz 2048
#define BL  (Bsz*Lsz)   // 524288 tokens

// ---------------- scratch ----------------
__device__ float g_Hf[(size_t)BL * 64];   // forward prestates [BL][64]
__device__ float g_Hb[(size_t)BL * 64];   // backward prestates
__device__ float g_T[4 * 64 * 64];
__device__ float g_gateW[68 * 256];       // folded gate weights [k][256]; cols: zf|htf|zb|htb
__device__ float g_gateB[256];
__device__ float g_headW[192 * 128];      // folded head weights [k][128] (rows 128.. used only for table build)
__device__ float g_headB[128];
__device__ float g_bp[64];                // sorted breakpoints
__device__ int   g_rank[64];              // rank of breakpoint j in sorted order
__device__ float2 g_gateC[65 * 256];      // per-segment (c0,c1) for gate outputs
__device__ float2 g_headC[65 * 128];      // per-segment (c0,c1) for head outputs

// ---------------- prep: fold weights (parallel, unchanged from R4) ----------------
__global__ void prepA_kernel(const float* fwz, const float* fbz, const float* fwh, const float* fbh,
                             const float* bwz, const float* bbz, const float* bwh, const float* bbh,
                             const float* fpw, const float* fpb, const float* bpw, const float* bpb)
{
    const int tid = threadIdx.x;
    const int g = tid >> 6, i = tid & 63;
    const int bid = blockIdx.x;
    const float* A  = (g==0) ? fwz : (g==1) ? fwh : (g==2) ? bwz : bwh;
    const float* ab = (g==0) ? fbz : (g==1) ? fbh : (g==2) ? bbz : bbh;
    const float* P  = (g<2) ? fpw : bpw;
    const float* pb = (g<2) ? fpb : bpb;

    if (bid < 64) {
        const int j = bid;
        float s = 0.f;
#pragma unroll 8
        for (int h = 0; h < 64; ++h) s = fmaf(A[i*64+h], P[h*67 + 3 + j], s);
        g_T[(size_t)(g*64+i)*64 + j] = s;
    } else if (bid < 67) {
        const int c = bid - 64;
        float s = 0.f;
#pragma unroll 8
        for (int h = 0; h < 64; ++h) s = fmaf(A[i*64+h], P[h*67 + c], s);
        g_gateW[c*256 + g*64 + i] = s;
    } else {
        float s = ab[i];
#pragma unroll 8
        for (int h = 0; h < 64; ++h) s = fmaf(A[i*64+h], pb[h], s);
        g_gateB[g*64 + i] = s;
        g_gateW[67*256 + tid] = 0.f;
    }
}

__global__ void prepB_kernel(const float* tew2, const float* teb2)
{
    const int o = threadIdx.x;
    const int bid = blockIdx.x;
    const float* T = &g_T[(size_t)o * 64];
    if (bid < 64) {
        const int k = bid;
        float s = 0.f;
#pragma unroll 8
        for (int j = 0; j < 64; ++j) s = fmaf(T[j], tew2[j*64 + k], s);
        g_gateW[(3+k)*256 + o] = s;
    } else {
        float s = 0.f;
#pragma unroll 8
        for (int j = 0; j < 64; ++j) s = fmaf(T[j], teb2[j], s);
        g_gateB[o] += s;
    }
}

__global__ void prepHead_kernel(const float* ghw1, const float* ghb1,
                                const float* tew2, const float* teb2)
{
    const int o = threadIdx.x;
    const int bid = blockIdx.x;
    if (bid < 64) {
        const int k = bid;
        float s = 0.f;
#pragma unroll 8
        for (int j = 0; j < 64; ++j) s = fmaf(ghw1[o*192 + 128 + j], tew2[j*64 + k], s);
        g_headW[(128+k)*128 + o] = s;
    } else if (bid == 64) {
        for (int k = 0; k < 128; ++k) g_headW[k*128 + o] = ghw1[o*192 + k];
    } else {
        float s = ghb1[o];
#pragma unroll 8
        for (int j = 0; j < 64; ++j) s = fmaf(ghw1[o*192 + 128 + j], teb2[j], s);
        g_headB[o] = s;
    }
}

// ---------------- PWL table construction ----------------
__global__ void prepBP_kernel(const float* tew1, const float* teb1)
{
    __shared__ float bpv[64];
    const int k = threadIdx.x;           // 64 threads
    const float a = tew1[k], b = teb1[k];
    const float v = (a != 0.f) ? (-b / a) : -1e38f;
    bpv[k] = v;
    __syncthreads();
    int r = 0;
    for (int j = 0; j < 64; ++j) {
        float u = bpv[j];
        if (u < v || (u == v && j < k)) ++r;
    }
    g_bp[r] = v;
    g_rank[k] = r;
}

// grid 65 x 256: segment s, output o. active(j,s) via exact rank test.
__global__ void prepGateTab_kernel(const float* tew1, const float* teb1)
{
    const int s = blockIdx.x, o = threadIdx.x;
    float c0 = 0.f, c1 = 0.f;
    for (int j = 0; j < 64; ++j) {
        const float a = tew1[j], b = teb1[j];
        const int rj = g_rank[j];
        const bool act = (a == 0.f) ? (b > 0.f) : ((a > 0.f) ? (s > rj) : (s <= rj));
        if (act) {
            const float m = g_gateW[(3+j)*256 + o];
            c0 = fmaf(m, b, c0);
            c1 = fmaf(m, a, c1);
        }
    }
    g_gateC[s*256 + o] = make_float2(c0, c1);
}

__global__ void prepHeadTab_kernel(const float* tew1, const float* teb1)
{
    const int s = blockIdx.x, o = threadIdx.x;   // 128 threads
    float c0 = 0.f, c1 = 0.f;
    for (int j = 0; j < 64; ++j) {
        const float a = tew1[j], b = teb1[j];
        const int rj = g_rank[j];
        const bool act = (a == 0.f) ? (b > 0.f) : ((a > 0.f) ? (s > rj) : (s <= rj));
        if (act) {
            const float m = g_headW[(128+j)*128 + o];
            c0 = fmaf(m, b, c0);
            c1 = fmaf(m, a, c1);
        }
    }
    g_headC[s*128 + o] = make_float2(c0, c1);
}

// ---------------- fused gates (PWL) + scan ----------------
// grid (256, 2) = (batch, dir); 512 threads, 2 blocks/SM.
#define Z_LD 129
#define FUSED_SMEM (2 * 64 * Z_LD * 4)   // zsm + hsm = 66048 B

__global__ void __launch_bounds__(512, 2)
fused_kernel(const float* __restrict__ x, const float* __restrict__ tt,
             const float* __restrict__ mtok)
{
    extern __shared__ float sm[];
    float* zsm = sm;                 // [64][129]
    float* hsm = sm + 64*Z_LD;       // [64][129]
    __shared__ float bp[64];
    __shared__ float x0s[128], x1s[128], ms[128], ts[128];
    __shared__ int   segs[128];
    __shared__ float mtk[2];

    const int tid = threadIdx.x;
    const int b = blockIdx.x;
    const int dir = blockIdx.y;

    if (tid < 64) bp[tid] = g_bp[tid];
    if (tid < 2)  mtk[tid] = mtok[tid];

    const int lane = tid & 31;
    const int wrp  = tid >> 5;
    const int o0 = lane * 4;           // 4 outputs per lane (of this dir's 128)
    const int t0 = wrp * 8;            // 8 tokens per warp
    const bool isz = (lane < 16);      // outs 0..63 -> z (sigmoid), 64..127 -> htilde (tanh)

    // per-thread constants
    float w0[4], w1[4], w2[4], bb[4];
#pragma unroll
    for (int i = 0; i < 4; ++i) {
        w0[i] = g_gateW[0*256 + dir*128 + o0 + i];
        w1[i] = g_gateW[1*256 + dir*128 + o0 + i];
        w2[i] = g_gateW[2*256 + dir*128 + o0 + i];
        bb[i] = g_gateB[dir*128 + o0 + i];
    }
    __syncthreads();

    float* Hout = (dir ? g_Hb : g_Hf) + (size_t)b * Lsz * 64;
    float* dst = isz ? zsm : hsm;
    const int chb = isz ? o0 : (o0 - 64);
    float hcar = 0.f;

    for (int ci = 0; ci < 16; ++ci) {
        const int c = dir ? (15 - ci) : ci;
        const size_t gb = (size_t)b * Lsz + (size_t)c * 128;

        if (tid < 128) {       // token prep + segment search
            const size_t g = gb + tid;
            float m  = x[g*3 + 2];
            float x0 = x[g*3 + 0];
            float x1 = x[g*3 + 1];
            if (m == 0.f) { x0 = mtk[0]; x1 = mtk[1]; }
            const float tv = tt[g];
            x0s[tid] = x0; x1s[tid] = x1; ms[tid] = m; ts[tid] = tv;
            int s = 0;
#pragma unroll
            for (int st = 32; st; st >>= 1)
                if (bp[s + st - 1] < tv) s += st;
            segs[tid] = s;
        }
        __syncthreads();

        // gate compute: PWL + 3-term x part
#pragma unroll 2
        for (int u = 0; u < 8; ++u) {
            const int tok = t0 + u;
            const int s = segs[tok];
            const float tv = ts[tok], x0 = x0s[tok], x1 = x1s[tok], mv = ms[tok];
            const float4* cp = (const float4*)&g_gateC[(size_t)s*256 + dir*128 + o0];
            const float4 ca = cp[0], cb = cp[1];
            float pre[4];
            pre[0] = fmaf(ca.y, tv, ca.x);
            pre[1] = fmaf(ca.w, tv, ca.z);
            pre[2] = fmaf(cb.y, tv, cb.x);
            pre[3] = fmaf(cb.w, tv, cb.z);
#pragma unroll
            for (int i = 0; i < 4; ++i) {
                float v = pre[i] + bb[i];
                v = fmaf(w0[i], x0, v);
                v = fmaf(w1[i], x1, v);
                v = fmaf(w2[i], mv, v);
                if (isz) {
                    v = __fdividef(1.f, 1.f + __expf(-v));
                } else {
                    float e = __expf(-2.f * fabsf(v));
                    v = copysignf(__fdividef(1.f - e, 1.f + e), v);
                }
                dst[(chb + i)*Z_LD + tok] = v;
            }
        }
        __syncthreads();

        if (tid < 64) {        // scan this chunk; ch = tid
            const float* zr = zsm + tid*Z_LD;
            const float* qr = hsm + tid*Z_LD;
            float* ho = Hout + (size_t)c*128*64 + tid;
            float h = hcar;
            if (dir == 0) {
#pragma unroll 4
                for (int t = 0; t < 128; ++t) {
                    ho[(size_t)t*64] = h;
                    h = fmaf(zr[t], qr[t] - h, h);
                }
            } else {
#pragma unroll 4
                for (int t = 127; t >= 0; --t) {
                    ho[(size_t)t*64] = h;
                    h = fmaf(zr[t], qr[t] - h, h);
                }
            }
            hcar = h;
        }
        __syncthreads();
    }
}

// ---------------- head GEMM: 128 outs x K=128 + PWL epilogue + fused 128->1 reduce ----------------
#define HEAD_SMEM ((128*128 + 128*128) * 4)

__global__ void __launch_bounds__(512, 1)
head_kernel(const float* __restrict__ x, const float* __restrict__ tt,
            const float* __restrict__ ghw2, const float* __restrict__ ghb2,
            float* __restrict__ out)
{
    extern __shared__ float sm[];
    float* Wsm = sm;                      // [128][128]
    float* Asm = Wsm + 128*128;           // [128][128]
    __shared__ __align__(16) float hff[64];
    __shared__ __align__(16) float hbf[64];
    __shared__ float w2sm[128];
    __shared__ float bsm[128];
    __shared__ float bp[64];
    __shared__ float ts[128];
    __shared__ int   segs[128];
    const int tid = threadIdx.x;
    const size_t base = (size_t)blockIdx.x * 128;
    const int b = (int)(base / Lsz);      // 2048 % 128 == 0

    for (int i = tid; i < 128*128/4; i += 512)
        ((float4*)Wsm)[i] = ((const float4*)g_headW)[i];

    if (tid < 64)        hff[tid]      = g_Hf[((size_t)b*Lsz + (Lsz-1))*64 + tid];
    else if (tid < 128)  hbf[tid - 64] = g_Hb[(size_t)b*Lsz*64 + (tid - 64)];
    else if (tid < 256)  ts[tid - 128] = tt[base + tid - 128];
    else if (tid < 384)  w2sm[tid-256] = ghw2[tid-256];
    else                 bsm[tid-384]  = g_headB[tid-384];
    if (tid >= 448)      bp[tid-448]   = g_bp[tid-448];
    __syncthreads();

    {
        const int tok  = tid & 127;
        const int part = tid >> 7;
        if (part < 2) {       // rows 0-63 h_fwd, 64-127 h_bwd (mask-substituted)
            const size_t g = base + tok;
            const float m  = x[g*3 + 2];
            const bool um  = m > 0.f;
            const float* src = (part ? g_Hb : g_Hf) + g * 64;
            const float* fin = part ? hbf : hff;
#pragma unroll
            for (int k = 0; k < 64; k += 4) {
                float4 v = *(const float4*)(src + k);
                float4 f = *(const float4*)(fin + k);
                float4 w = um ? v : f;
                int row = part*64 + k;
                Asm[(row+0)*128 + tok] = w.x;
                Asm[(row+1)*128 + tok] = w.y;
                Asm[(row+2)*128 + tok] = w.z;
                Asm[(row+3)*128 + tok] = w.w;
            }
        } else if (part == 2) {   // segment search for token tok
            const float tv = ts[tok];
            int s = 0;
#pragma unroll
            for (int st = 32; st; st >>= 1)
                if (bp[s + st - 1] < tv) s += st;
            segs[tok] = s;
        }
    }
    __syncthreads();

    const int lane = tid & 31;
    const int wrp  = tid >> 5;
    const int o0 = lane * 4;
    const int t0 = wrp * 8;
    float acc[4][8];
#pragma unroll
    for (int i = 0; i < 4; ++i)
#pragma unroll
        for (int j = 0; j < 8; ++j) acc[i][j] = 0.f;

#pragma unroll 4
    for (int k = 0; k < 128; ++k) {
        float4 wv = *(const float4*)&Wsm[k*128 + o0];
        float4 a0 = *(const float4*)&Asm[k*128 + t0];
        float4 a1 = *(const float4*)&Asm[k*128 + t0 + 4];
        float a[8] = {a0.x,a0.y,a0.z,a0.w,a1.x,a1.y,a1.z,a1.w};
        float w[4] = {wv.x,wv.y,wv.z,wv.w};
#pragma unroll
        for (int oi = 0; oi < 4; ++oi)
#pragma unroll
            for (int tj = 0; tj < 8; ++tj)
                acc[oi][tj] = fmaf(w[oi], a[tj], acc[oi][tj]);
    }

    float w2[4], bb[4];
#pragma unroll
    for (int oi = 0; oi < 4; ++oi) { w2[oi] = w2sm[o0+oi]; bb[oi] = bsm[o0+oi]; }
    const float outb = ghb2[0];

#pragma unroll
    for (int tj = 0; tj < 8; ++tj) {
        const int tok = t0 + tj;
        const int sg = segs[tok];
        const float tv = ts[tok];
        const float4* cp = (const float4*)&g_headC[(size_t)sg*128 + o0];
        const float4 ca = cp[0], cb = cp[1];
        float pw[4];
        pw[0] = fmaf(ca.y, tv, ca.x);
        pw[1] = fmaf(ca.w, tv, ca.z);
        pw[2] = fmaf(cb.y, tv, cb.x);
        pw[3] = fmaf(cb.w, tv, cb.z);
        float s = 0.f;
#pragma unroll
        for (int oi = 0; oi < 4; ++oi)
            s = fmaf(w2[oi], fmaxf(acc[oi][tj] + bb[oi] + pw[oi], 0.f), s);
#pragma unroll
        for (int off = 16; off > 0; off >>= 1)
            s += __shfl_xor_sync(0xffffffffu, s, off);
        if (lane == 0) out[base + tok] = s + outb;
    }
}

// ---------------- launch ----------------
extern "C" void kernel_launch(void* const* d_in, const int* in_sizes, int n_in,
                              void* d_out, int out_size)
{
    (void)in_sizes; (void)n_in; (void)out_size;
    const float* x    = (const float*)d_in[0];
    const float* t    = (const float*)d_in[1];
    const float* mtok = (const float*)d_in[2];
    const float* tew1 = (const float*)d_in[3];
    const float* teb1 = (const float*)d_in[4];
    const float* tew2 = (const float*)d_in[5];
    const float* teb2 = (const float*)d_in[6];
    const float* fpw  = (const float*)d_in[7];
    const float* fpb  = (const float*)d_in[8];
    const float* bpw  = (const float*)d_in[9];
    const float* bpb  = (const float*)d_in[10];
    const float* fwz  = (const float*)d_in[11];
    const float* fbz  = (const float*)d_in[12];
    const float* fwh  = (const float*)d_in[13];
    const float* fbh  = (const float*)d_in[14];
    const float* bwz  = (const float*)d_in[15];
    const float* bbz  = (const float*)d_in[16];
    const float* bwh  = (const float*)d_in[17];
    const float* bbh  = (const float*)d_in[18];
    const float* ghw1 = (const float*)d_in[19];
    const float* ghb1 = (const float*)d_in[20];
    const float* ghw2 = (const float*)d_in[21];
    const float* ghb2 = (const float*)d_in[22];
    float* out = (float*)d_out;

    cudaFuncSetAttribute(fused_kernel, cudaFuncAttributeMaxDynamicSharedMemorySize, FUSED_SMEM);
    cudaFuncSetAttribute(head_kernel,  cudaFuncAttributeMaxDynamicSharedMemorySize, HEAD_SMEM);

    prepA_kernel<<<68, 256>>>(fwz, fbz, fwh, fbh, bwz, bbz, bwh, bbh, fpw, fpb, bpw, bpb);
    prepB_kernel<<<65, 256>>>(tew2, teb2);
    prepHead_kernel<<<66, 128>>>(ghw1, ghb1, tew2, teb2);
    prepBP_kernel<<<1, 64>>>(tew1, teb1);
    prepGateTab_kernel<<<65, 256>>>(tew1, teb1);
    prepHeadTab_kernel<<<65, 128>>>(tew1, teb1);

    fused_kernel<<<dim3(Bsz, 2), 512, FUSED_SMEM>>>(x, t, mtok);
    head_kernel<<<BL/128, 512, HEAD_SMEM>>>(x, t, ghw2, ghb2, out);
}

// round 7
// speedup vs baseline: 3.5762x; 1.0471x over previous
#include <cuda_runtime.h>
#include <cuda_bf16.h>
#include <mma.h>
#include <cstddef>
#include <cstdint>
using namespace nvcuda;

#define Bsz 256
#define Lsz 2048
#define BL  (Bsz*Lsz)   // 524288 tokens

// ---------------- scratch ----------------
__device__ float g_Hf[(size_t)BL * 64];   // forward prestates [BL][64]
__device__ float g_Hb[(size_t)BL * 64];   // backward prestates
__device__ float g_T[4 * 64 * 64];
__device__ float g_gateW[68 * 256];       // folded gate weights [k][256]; cols: zf|htf|zb|htb
__device__ float g_gateB[256];
__device__ float g_headW[192 * 128];      // folded head weights [k][128] (rows 0..127 = GEMM part)
__device__ float g_headB[128];
__device__ float g_bp[64];                // sorted breakpoints
__device__ int   g_rank[64];
__device__ float2 g_gateC[65 * 256];      // per-segment (c0,c1) gate PWL table
__device__ float2 g_headC[65 * 128];      // per-segment (c0,c1) head PWL table
__device__ __nv_bfloat16 g_headWh[128 * 128];  // head W hi/lo, [k][128]
__device__ __nv_bfloat16 g_headWl[128 * 128];

// ---------------- prep: fold weights (parallel) ----------------
__global__ void prepA_kernel(const float* fwz, const float* fbz, const float* fwh, const float* fbh,
                             const float* bwz, const float* bbz, const float* bwh, const float* bbh,
                             const float* fpw, const float* fpb, const float* bpw, const float* bpb)
{
    const int tid = threadIdx.x;
    const int g = tid >> 6, i = tid & 63;
    const int bid = blockIdx.x;
    const float* A  = (g==0) ? fwz : (g==1) ? fwh : (g==2) ? bwz : bwh;
    const float* ab = (g==0) ? fbz : (g==1) ? fbh : (g==2) ? bbz : bbh;
    const float* P  = (g<2) ? fpw : bpw;
    const float* pb = (g<2) ? fpb : bpb;

    if (bid < 64) {
        const int j = bid;
        float s = 0.f;
#pragma unroll 8
        for (int h = 0; h < 64; ++h) s = fmaf(A[i*64+h], P[h*67 + 3 + j], s);
        g_T[(size_t)(g*64+i)*64 + j] = s;
    } else if (bid < 67) {
        const int c = bid - 64;
        float s = 0.f;
#pragma unroll 8
        for (int h = 0; h < 64; ++h) s = fmaf(A[i*64+h], P[h*67 + c], s);
        g_gateW[c*256 + g*64 + i] = s;
    } else {
        float s = ab[i];
#pragma unroll 8
        for (int h = 0; h < 64; ++h) s = fmaf(A[i*64+h], pb[h], s);
        g_gateB[g*64 + i] = s;
        g_gateW[67*256 + tid] = 0.f;
    }
}

__global__ void prepB_kernel(const float* tew2, const float* teb2)
{
    const int o = threadIdx.x;
    const int bid = blockIdx.x;
    const float* T = &g_T[(size_t)o * 64];
    if (bid < 64) {
        const int k = bid;
        float s = 0.f;
#pragma unroll 8
        for (int j = 0; j < 64; ++j) s = fmaf(T[j], tew2[j*64 + k], s);
        g_gateW[(3+k)*256 + o] = s;
    } else {
        float s = 0.f;
#pragma unroll 8
        for (int j = 0; j < 64; ++j) s = fmaf(T[j], teb2[j], s);
        g_gateB[o] += s;
    }
}

__global__ void prepHead_kernel(const float* ghw1, const float* ghb1,
                                const float* tew2, const float* teb2)
{
    const int o = threadIdx.x;
    const int bid = blockIdx.x;
    if (bid < 64) {
        const int k = bid;
        float s = 0.f;
#pragma unroll 8
        for (int j = 0; j < 64; ++j) s = fmaf(ghw1[o*192 + 128 + j], tew2[j*64 + k], s);
        g_headW[(128+k)*128 + o] = s;
    } else if (bid == 64) {
        for (int k = 0; k < 128; ++k) g_headW[k*128 + o] = ghw1[o*192 + k];
    } else {
        float s = ghb1[o];
#pragma unroll 8
        for (int j = 0; j < 64; ++j) s = fmaf(ghw1[o*192 + 128 + j], teb2[j], s);
        g_headB[o] = s;
    }
}

// parallel bf16 hi/lo split of head W rows 0..127  (grid 128 x 128 threads)
__global__ void convHead_kernel()
{
    const int k = blockIdx.x, o = threadIdx.x;
    const float w = g_headW[k*128 + o];
    const __nv_bfloat16 h = __float2bfloat16(w);
    g_headWh[k*128 + o] = h;
    g_headWl[k*128 + o] = __float2bfloat16(w - __bfloat162float(h));
}

// ---------------- PWL table construction ----------------
__global__ void prepBP_kernel(const float* tew1, const float* teb1)
{
    __shared__ float bpv[64];
    const int k = threadIdx.x;
    const float a = tew1[k], b = teb1[k];
    const float v = (a != 0.f) ? (-b / a) : -1e38f;
    bpv[k] = v;
    __syncthreads();
    int r = 0;
    for (int j = 0; j < 64; ++j) {
        float u = bpv[j];
        if (u < v || (u == v && j < k)) ++r;
    }
    g_bp[r] = v;
    g_rank[k] = r;
}

__global__ void prepGateTab_kernel(const float* tew1, const float* teb1)
{
    const int s = blockIdx.x, o = threadIdx.x;
    float c0 = 0.f, c1 = 0.f;
    for (int j = 0; j < 64; ++j) {
        const float a = tew1[j], b = teb1[j];
        const int rj = g_rank[j];
        const bool act = (a == 0.f) ? (b > 0.f) : ((a > 0.f) ? (s > rj) : (s <= rj));
        if (act) {
            const float m = g_gateW[(3+j)*256 + o];
            c0 = fmaf(m, b, c0);
            c1 = fmaf(m, a, c1);
        }
    }
    g_gateC[s*256 + o] = make_float2(c0, c1);
}

__global__ void prepHeadTab_kernel(const float* tew1, const float* teb1)
{
    const int s = blockIdx.x, o = threadIdx.x;
    float c0 = 0.f, c1 = 0.f;
    for (int j = 0; j < 64; ++j) {
        const float a = tew1[j], b = teb1[j];
        const int rj = g_rank[j];
        const bool act = (a == 0.f) ? (b > 0.f) : ((a > 0.f) ? (s > rj) : (s <= rj));
        if (act) {
            const float m = g_headW[(128+j)*128 + o];
            c0 = fmaf(m, b, c0);
            c1 = fmaf(m, a, c1);
        }
    }
    g_headC[s*128 + o] = make_float2(c0, c1);
}

// ---------------- fused gates (PWL) + scan (unchanged, R5-proven) ----------------
#define Z_LD 129
#define FUSED_SMEM (2 * 64 * Z_LD * 4)

__global__ void __launch_bounds__(512, 2)
fused_kernel(const float* __restrict__ x, const float* __restrict__ tt,
             const float* __restrict__ mtok)
{
    extern __shared__ float sm[];
    float* zsm = sm;
    float* hsm = sm + 64*Z_LD;
    __shared__ float bp[64];
    __shared__ float x0s[128], x1s[128], ms[128], ts[128];
    __shared__ int   segs[128];
    __shared__ float mtk[2];

    const int tid = threadIdx.x;
    const int b = blockIdx.x;
    const int dir = blockIdx.y;

    if (tid < 64) bp[tid] = g_bp[tid];
    if (tid < 2)  mtk[tid] = mtok[tid];

    const int lane = tid & 31;
    const int wrp  = tid >> 5;
    const int o0 = lane * 4;
    const int t0 = wrp * 8;
    const bool isz = (lane < 16);

    float w0[4], w1[4], w2[4], bb[4];
#pragma unroll
    for (int i = 0; i < 4; ++i) {
        w0[i] = g_gateW[0*256 + dir*128 + o0 + i];
        w1[i] = g_gateW[1*256 + dir*128 + o0 + i];
        w2[i] = g_gateW[2*256 + dir*128 + o0 + i];
        bb[i] = g_gateB[dir*128 + o0 + i];
    }
    __syncthreads();

    float* Hout = (dir ? g_Hb : g_Hf) + (size_t)b * Lsz * 64;
    float* dst = isz ? zsm : hsm;
    const int chb = isz ? o0 : (o0 - 64);
    float hcar = 0.f;

    for (int ci = 0; ci < 16; ++ci) {
        const int c = dir ? (15 - ci) : ci;
        const size_t gb = (size_t)b * Lsz + (size_t)c * 128;

        if (tid < 128) {
            const size_t g = gb + tid;
            float m  = x[g*3 + 2];
            float x0 = x[g*3 + 0];
            float x1 = x[g*3 + 1];
            if (m == 0.f) { x0 = mtk[0]; x1 = mtk[1]; }
            const float tv = tt[g];
            x0s[tid] = x0; x1s[tid] = x1; ms[tid] = m; ts[tid] = tv;
            int s = 0;
#pragma unroll
            for (int st = 32; st; st >>= 1)
                if (bp[s + st - 1] < tv) s += st;
            segs[tid] = s;
        }
        __syncthreads();

#pragma unroll 2
        for (int u = 0; u < 8; ++u) {
            const int tok = t0 + u;
            const int s = segs[tok];
            const float tv = ts[tok], x0 = x0s[tok], x1 = x1s[tok], mv = ms[tok];
            const float4* cp = (const float4*)&g_gateC[(size_t)s*256 + dir*128 + o0];
            const float4 ca = cp[0], cb = cp[1];
            float pre[4];
            pre[0] = fmaf(ca.y, tv, ca.x);
            pre[1] = fmaf(ca.w, tv, ca.z);
            pre[2] = fmaf(cb.y, tv, cb.x);
            pre[3] = fmaf(cb.w, tv, cb.z);
#pragma unroll
            for (int i = 0; i < 4; ++i) {
                float v = pre[i] + bb[i];
                v = fmaf(w0[i], x0, v);
                v = fmaf(w1[i], x1, v);
                v = fmaf(w2[i], mv, v);
                if (isz) {
                    v = __fdividef(1.f, 1.f + __expf(-v));
                } else {
                    float e = __expf(-2.f * fabsf(v));
                    v = copysignf(__fdividef(1.f - e, 1.f + e), v);
                }
                dst[(chb + i)*Z_LD + tok] = v;
            }
        }
        __syncthreads();

        if (tid < 64) {
            const float* zr = zsm + tid*Z_LD;
            const float* qr = hsm + tid*Z_LD;
            float* ho = Hout + (size_t)c*128*64 + tid;
            float h = hcar;
            if (dir == 0) {
#pragma unroll 4
                for (int t = 0; t < 128; ++t) {
                    ho[(size_t)t*64] = h;
                    h = fmaf(zr[t], qr[t] - h, h);
                }
            } else {
#pragma unroll 4
                for (int t = 127; t >= 0; --t) {
                    ho[(size_t)t*64] = h;
                    h = fmaf(zr[t], qr[t] - h, h);
                }
            }
            hcar = h;
        }
        __syncthreads();
    }
}

// ---------------- head: wmma bf16x3 GEMM, M=128 tok x N=128 outs x K=128 ----------------
#define HW_LDA 136
#define HC_LDC 132
#define HEAD_SMEM (2*128*HW_LDA*2 + 2*128*128*2)   // Ah+Al (69632) + Wh+Wl (65536) = 135168

__global__ void __launch_bounds__(256, 1)
head_kernel(const float* __restrict__ x, const float* __restrict__ tt,
            const float* __restrict__ ghw2, const float* __restrict__ ghb2,
            float* __restrict__ out)
{
    extern __shared__ char smraw[];
    __nv_bfloat16* Ah = (__nv_bfloat16*)smraw;            // [128][136]
    __nv_bfloat16* Al = Ah + 128*HW_LDA;
    __nv_bfloat16* Wh = Al + 128*HW_LDA;                  // [128][128]
    __nv_bfloat16* Wl = Wh + 128*128;
    float* Csm = (float*)smraw;                            // reuse A region: [128][132] = 67584 B
    __shared__ __align__(16) float hff[64];
    __shared__ __align__(16) float hbf[64];
    __shared__ float ts[128];
    __shared__ int   segs[128];
    __shared__ float w2s[128], bbs[128], bp[64];

    const int tid = threadIdx.x;
    const size_t base = (size_t)blockIdx.x * 128;
    const int b = (int)(base >> 11);      // 2048 tokens per batch, 128 | 2048

    {   // stage W hi/lo: 2048 float4 each
        const float4* sh = (const float4*)g_headWh;
        const float4* sl = (const float4*)g_headWl;
        float4* dh = (float4*)Wh;
        float4* dl = (float4*)Wl;
        for (int i = tid; i < 2048; i += 256) { dh[i] = sh[i]; dl[i] = sl[i]; }
    }
    if (tid < 64) {
        bp[tid]  = g_bp[tid];
        hff[tid] = g_Hf[(((size_t)b << 11) + (Lsz-1))*64 + tid];
        hbf[tid] = g_Hb[((size_t)b << 11)*64 + tid];
    }
    if (tid < 128) { w2s[tid] = ghw2[tid]; bbs[tid] = g_headB[tid]; }
    __syncthreads();

    {   // build A hi/lo: token r = tid&127, half hf = tid>>7 covers 64 K-cols
        const int r  = tid & 127;
        const int hf = tid >> 7;
        const size_t g = base + r;
        const float m = x[g*3 + 2];
        const bool um = m > 0.f;
        if (hf == 0) {
            const float tv = tt[g];
            ts[r] = tv;
            int s = 0;
#pragma unroll
            for (int st = 32; st; st >>= 1)
                if (bp[s + st - 1] < tv) s += st;
            segs[r] = s;
        }
        const float* srcg = (hf ? g_Hb : g_Hf) + g*64;
        const float* fin  = hf ? hbf : hff;
        __nv_bfloat16* dh = Ah + r*HW_LDA + hf*64;
        __nv_bfloat16* dl = Al + r*HW_LDA + hf*64;
#pragma unroll
        for (int kg = 0; kg < 8; ++kg) {
            float4 v0 = ((const float4*)srcg)[kg*2];
            float4 v1 = ((const float4*)srcg)[kg*2 + 1];
            if (!um) {
                v0 = ((const float4*)fin)[kg*2];
                v1 = ((const float4*)fin)[kg*2 + 1];
            }
            float vv[8] = {v0.x,v0.y,v0.z,v0.w,v1.x,v1.y,v1.z,v1.w};
            union { uint4 q; __nv_bfloat162 b2[4]; } uh, ul;
#pragma unroll
            for (int j = 0; j < 4; ++j) {
                const float a0 = vv[2*j], a1 = vv[2*j+1];
                const __nv_bfloat16 h0 = __float2bfloat16(a0);
                const __nv_bfloat16 h1 = __float2bfloat16(a1);
                uh.b2[j] = __halves2bfloat162(h0, h1);
                ul.b2[j] = __halves2bfloat162(__float2bfloat16(a0 - __bfloat162float(h0)),
                                              __float2bfloat16(a1 - __bfloat162float(h1)));
            }
            *(uint4*)(dh + kg*8) = uh.q;
            *(uint4*)(dl + kg*8) = ul.q;
        }
    }
    __syncthreads();

    // 8 warps: wm = wrp>>2 (2 row tiles of 64), wn = wrp&3 (4 col tiles of 32)
    const int wrp = tid >> 5;
    const int wm = wrp >> 2;
    const int wn = wrp & 3;

    wmma::fragment<wmma::accumulator,16,16,16,float> acc[4][2];
#pragma unroll
    for (int i = 0; i < 4; ++i)
#pragma unroll
        for (int j = 0; j < 2; ++j) wmma::fill_fragment(acc[i][j], 0.f);

#pragma unroll
    for (int ks = 0; ks < 8; ++ks) {
        wmma::fragment<wmma::matrix_a,16,16,16,__nv_bfloat16,wmma::row_major> fah[4], fal[4];
#pragma unroll
        for (int i = 0; i < 4; ++i) {
            wmma::load_matrix_sync(fah[i], Ah + (wm*64 + i*16)*HW_LDA + ks*16, HW_LDA);
            wmma::load_matrix_sync(fal[i], Al + (wm*64 + i*16)*HW_LDA + ks*16, HW_LDA);
        }
#pragma unroll
        for (int j = 0; j < 2; ++j) {
            wmma::fragment<wmma::matrix_b,16,16,16,__nv_bfloat16,wmma::row_major> fbh, fbl;
            wmma::load_matrix_sync(fbh, Wh + (ks*16)*128 + wn*32 + j*16, 128);
            wmma::load_matrix_sync(fbl, Wl + (ks*16)*128 + wn*32 + j*16, 128);
#pragma unroll
            for (int i = 0; i < 4; ++i) {
                wmma::mma_sync(acc[i][j], fah[i], fbh, acc[i][j]);
                wmma::mma_sync(acc[i][j], fah[i], fbl, acc[i][j]);
                wmma::mma_sync(acc[i][j], fal[i], fbh, acc[i][j]);
            }
        }
    }
    __syncthreads();   // A dead -> Csm
#pragma unroll
    for (int i = 0; i < 4; ++i)
#pragma unroll
        for (int j = 0; j < 2; ++j)
            wmma::store_matrix_sync(Csm + (wm*64 + i*16)*HC_LDC + wn*32 + j*16,
                                    acc[i][j], HC_LDC, wmma::mem_row_major);
    __syncthreads();

    // fused epilogue: out[tok] = ghb2 + sum_o w2[o]*relu(C[tok][o] + bb[o] + pwl(o,t))
    {
        const int token = tid >> 1;
        const int half  = tid & 1;
        const int sg = segs[token];
        const float tv = ts[token];
        float s = 0.f;
#pragma unroll
        for (int o4 = 0; o4 < 64; o4 += 4) {
            const int o = half*64 + o4;
            float4 c = *(float4*)&Csm[token*HC_LDC + o];
            const float4* cp = (const float4*)&g_headC[(size_t)sg*128 + o];
            const float4 p0 = cp[0], p1 = cp[1];
            s = fmaf(w2s[o+0], fmaxf(c.x + bbs[o+0] + fmaf(p0.y, tv, p0.x), 0.f), s);
            s = fmaf(w2s[o+1], fmaxf(c.y + bbs[o+1] + fmaf(p0.w, tv, p0.z), 0.f), s);
            s = fmaf(w2s[o+2], fmaxf(c.z + bbs[o+2] + fmaf(p1.y, tv, p1.x), 0.f), s);
            s = fmaf(w2s[o+3], fmaxf(c.w + bbs[o+3] + fmaf(p1.w, tv, p1.z), 0.f), s);
        }
        s += __shfl_xor_sync(0xffffffffu, s, 1);
        if (half == 0) out[base + token] = s + ghb2[0];
    }
}

// ---------------- launch ----------------
extern "C" void kernel_launch(void* const* d_in, const int* in_sizes, int n_in,
                              void* d_out, int out_size)
{
    (void)in_sizes; (void)n_in; (void)out_size;
    const float* x    = (const float*)d_in[0];
    const float* t    = (const float*)d_in[1];
    const float* mtok = (const float*)d_in[2];
    const float* tew1 = (const float*)d_in[3];
    const float* teb1 = (const float*)d_in[4];
    const float* tew2 = (const float*)d_in[5];
    const float* teb2 = (const float*)d_in[6];
    const float* fpw  = (const float*)d_in[7];
    const float* fpb  = (const float*)d_in[8];
    const float* bpw  = (const float*)d_in[9];
    const float* bpb  = (const float*)d_in[10];
    const float* fwz  = (const float*)d_in[11];
    const float* fbz  = (const float*)d_in[12];
    const float* fwh  = (const float*)d_in[13];
    const float* fbh  = (const float*)d_in[14];
    const float* bwz  = (const float*)d_in[15];
    const float* bbz  = (const float*)d_in[16];
    const float* bwh  = (const float*)d_in[17];
    const float* bbh  = (const float*)d_in[18];
    const float* ghw1 = (const float*)d_in[19];
    const float* ghb1 = (const float*)d_in[20];
    const float* ghw2 = (const float*)d_in[21];
    const float* ghb2 = (const float*)d_in[22];
    float* out = (float*)d_out;

    cudaFuncSetAttribute(fused_kernel, cudaFuncAttributeMaxDynamicSharedMemorySize, FUSED_SMEM);
    cudaFuncSetAttribute(head_kernel,  cudaFuncAttributeMaxDynamicSharedMemorySize, HEAD_SMEM);

    prepA_kernel<<<68, 256>>>(fwz, fbz, fwh, fbh, bwz, bbz, bwh, bbh, fpw, fpb, bpw, bpb);
    prepB_kernel<<<65, 256>>>(tew2, teb2);
    prepHead_kernel<<<66, 128>>>(ghw1, ghb1, tew2, teb2);
    convHead_kernel<<<128, 128>>>();
    prepBP_kernel<<<1, 64>>>(tew1, teb1);
    prepGateTab_kernel<<<65, 256>>>(tew1, teb1);
    prepHeadTab_kernel<<<65, 128>>>(tew1, teb1);

    fused_kernel<<<dim3(Bsz, 2), 512, FUSED_SMEM>>>(x, t, mtok);
    head_kernel<<<BL/128, 256, HEAD_SMEM>>>(x, t, ghw2, ghb2, out);
}